// round 11
// baseline (speedup 1.0000x reference)
#include <cuda_runtime.h>
#include <math.h>

#define EPS 1e-6f
#define COLSB 128
#define ROWS 4
#define RBPP (COLSB / ROWS)  // row-blocks per full panel step

// Interval endpoints, defer-snap formulation (decision-exact vs snapped ref):
//   valid_k == !(same nonzero sign) & !(both zero)
//   t_k = z_i ? p_i : (z_j ? p_j : p_i + (p_j-p_i)*d_i/(d_i-d_j))
// For |d|>=EPS both raw==snapped, formula identical; zero cases give exactly
// the endpoint the snapped formula produces.
__device__ __forceinline__ void interval3(const float p[3], const float d[3],
                                          const bool pp[3], const bool nn[3],
                                          const bool zz[3],
                                          float& tmin, float& tmax) {
    tmin = INFINITY;
    tmax = -INFINITY;
#pragma unroll
    for (int k = 0; k < 3; k++) {
        const int kn = (k == 2) ? 0 : k + 1;
        bool valid = !((pp[k] & pp[kn]) | (nn[k] & nn[kn])) & !(zz[k] & zz[kn]);
        float tf = p[k] + (p[kn] - p[k]) * __fdividef(d[k], d[k] - d[kn]);
        float t = zz[k] ? p[k] : (zz[kn] ? p[kn] : tf);
        if (valid) {
            tmin = fminf(tmin, t);
            tmax = fmaxf(tmax, t);
        }
    }
}

__device__ __forceinline__ float sel3(int ax, float x, float y, float z) {
    return (ax == 0) ? x : ((ax == 1) ? y : z);
}

// Core pair test: row triangle via 3x LDS.128 (padded row), B in registers.
__device__ __forceinline__ bool pair_test(const float4* __restrict__ a4,
                                          const float4 na,
                                          const float* __restrict__ B,
                                          const float4 nb) {
    float4 A0 = a4[0], A1 = a4[1];
    float A8 = a4[2].x;
    float Av[3][3] = {{A0.x, A0.y, A0.z},
                      {A0.w, A1.x, A1.y},
                      {A1.z, A1.w, A8}};

    float dv[3], du[3];
    bool pv_[3], nv_[3], zv_[3], pu_[3], nu_[3], zu_[3];
#pragma unroll
    for (int v = 0; v < 3; v++) {
        float dd = Av[v][0] * nb.x + Av[v][1] * nb.y + Av[v][2] * nb.z + nb.w;
        dv[v] = dd;
        pv_[v] = dd >= EPS;
        nv_[v] = dd <= -EPS;
        zv_[v] = !(pv_[v] | nv_[v]);
        float ee = B[3 * v] * na.x + B[3 * v + 1] * na.y +
                   B[3 * v + 2] * na.z + na.w;
        du[v] = ee;
        pu_[v] = ee >= EPS;
        nu_[v] = ee <= -EPS;
        zu_[v] = !(pu_[v] | nu_[v]);
    }

    bool ssv = (pv_[0] & pv_[1] & pv_[2]) | (nv_[0] & nv_[1] & nv_[2]);
    bool ssu = (pu_[0] & pu_[1] & pu_[2]) | (nu_[0] & nu_[1] & nu_[2]);

    // Dominant axis of na x nb (first-max argmax).
    float Dx = na.y * nb.z - na.z * nb.y;
    float Dy = na.z * nb.x - na.x * nb.z;
    float Dz = na.x * nb.y - na.y * nb.x;
    int ax = 0;
    float m = fabsf(Dx);
    if (fabsf(Dy) > m) { ax = 1; m = fabsf(Dy); }
    if (fabsf(Dz) > m) { ax = 2; }

    float pv[3], pu[3];
#pragma unroll
    for (int v = 0; v < 3; v++) {
        pv[v] = sel3(ax, Av[v][0], Av[v][1], Av[v][2]);
        pu[v] = sel3(ax, B[3 * v], B[3 * v + 1], B[3 * v + 2]);
    }

    float t0v, t1v, t0u, t1u;
    interval3(pv, dv, pv_, nv_, zv_, t0v, t1v);
    interval3(pu, du, pu_, nu_, zu_, t0u, t1u);
    return !ssv & !ssu & (fmaxf(t0v, t0u) <= fminf(t1v, t1u));
}

// Cumulative row-block count before panel p (valid for full panels).
__device__ __forceinline__ int cum_rb(int p) { return RBPP * p * (p + 1) / 2; }

__global__ __launch_bounds__(COLSB, 14)
void pair_kernel(const float* __restrict__ T, float* __restrict__ out,
                 int N, int P) {
    // O(1) decode: linear tile id -> (panel p, row-block).
    const int k = blockIdx.x;
    int p = (int)((sqrtf(1.0f + (8.0f / RBPP) * (float)k) - 1.0f) * 0.5f);
    if (p > P - 1) p = P - 1;
    while (p + 1 <= P - 1 && cum_rb(p + 1) <= k) p++;
    while (p > 0 && cum_rb(p) > k) p--;
    const int c0 = p * COLSB;
    const int r0 = (k - cum_rb(p)) * ROWS;

    __shared__ float sA[ROWS][12];   // padded to 48B rows for LDS.128
    __shared__ float4 sP[ROWS];

    const int tid = threadIdx.x;

    if (tid < ROWS * 12) {
        int r = tid / 12, c = tid % 12;
        int gi = r0 + r;
        sA[r][c] = (c < 9 && gi < N) ? T[(size_t)gi * 9 + c] : 0.0f;
    }
    __syncthreads();
    if (tid < ROWS) {
        const float* t = sA[tid];
        float e1x = t[3] - t[0], e1y = t[4] - t[1], e1z = t[5] - t[2];
        float e2x = t[6] - t[0], e2y = t[7] - t[1], e2z = t[8] - t[2];
        float nx = e1y * e2z - e1z * e2y;
        float ny = e1z * e2x - e1x * e2z;
        float nz = e1x * e2y - e1y * e2x;
        sP[tid] = make_float4(nx, ny, nz, -(nx * t[0] + ny * t[1] + nz * t[2]));
    }

    const int j = c0 + tid;
    const bool jok = j < N;
    const int jc = jok ? j : (N - 1);

    float B[9];
    const float* tb = T + (size_t)jc * 9;
#pragma unroll
    for (int c = 0; c < 9; c++) B[c] = __ldg(tb + c);
    float4 nb;
    {
        float e1x = B[3] - B[0], e1y = B[4] - B[1], e1z = B[5] - B[2];
        float e2x = B[6] - B[0], e2y = B[7] - B[1], e2z = B[8] - B[2];
        nb.x = e1y * e2z - e1z * e2y;
        nb.y = e1z * e2x - e1x * e2z;
        nb.z = e1x * e2y - e1y * e2x;
        nb.w = -(nb.x * B[0] + nb.y * B[1] + nb.z * B[2]);
    }
    __syncthreads();

    const bool interior = (r0 + ROWS <= c0) && (c0 + COLSB <= N);

    if (interior) {
        unsigned hitmask = 0;
#pragma unroll
        for (int r = 0; r < ROWS; r++) {
            bool hit = pair_test((const float4*)sA[r], sP[r], B, nb);
            hitmask |= (hit ? 1u : 0u) << r;
            out[(size_t)(r0 + r) * N + j] = hit ? 1.0f : 0.0f;  // coalesced
        }
        float4 v0;
        v0.x = (hitmask & 1u) ? 1.0f : 0.0f;
        v0.y = (hitmask & 2u) ? 1.0f : 0.0f;
        v0.z = (hitmask & 4u) ? 1.0f : 0.0f;
        v0.w = (hitmask & 8u) ? 1.0f : 0.0f;
        *(float4*)(out + (size_t)j * N + r0) = v0;
    } else {
        unsigned hitmask = 0;
#pragma unroll
        for (int r = 0; r < ROWS; r++) {
            const int i = r0 + r;
            bool hit = pair_test((const float4*)sA[r], sP[r], B, nb);
            hitmask |= (hit ? 1u : 0u) << r;
            float val = (i == j) ? 1.0f : (hit ? 1.0f : 0.0f);
            if (jok & (i <= j) & (i < N)) out[(size_t)i * N + j] = val;
        }
        if (jok) {
#pragma unroll
            for (int r = 0; r < ROWS; r++) {
                int i = r0 + r;
                if ((i < j) & (i < N))
                    out[(size_t)j * N + i] = (hitmask >> r & 1u) ? 1.0f : 0.0f;
            }
        }
    }
}

extern "C" void kernel_launch(void* const* d_in, const int* in_sizes, int n_in,
                              void* d_out, int out_size) {
    const float* T = (const float*)d_in[0];
    float* out = (float*)d_out;
    int N = in_sizes[0] / 9;

    int P = (N + COLSB - 1) / COLSB;
    int nblk = 0;
    for (int p = 0; p < P; p++) {
        int lim = (p + 1) * COLSB;
        if (lim > N) lim = N;
        nblk += (lim + ROWS - 1) / ROWS;
    }
    pair_kernel<<<nblk, COLSB>>>(T, out, N, P);
}

// round 12
// speedup vs baseline: 1.0088x; 1.0088x over previous
#include <cuda_runtime.h>
#include <math.h>

#define EPS 1e-6f
#define COLSB 256
#define HALFC 128
#define ROWS 4
#define RBPP (COLSB / ROWS)  // row-blocks per full panel step

typedef unsigned long long ull;

#define FMA2(d, a, b, c) \
    asm("fma.rn.f32x2 %0,%1,%2,%3;" : "=l"(d) : "l"(a), "l"(b), "l"(c))
#define PACK2(d, lo, hi) \
    asm("mov.b64 %0,{%1,%2};" : "=l"(d) : "f"(lo), "f"(hi))
#define UNPACK2(lo, hi, s) \
    asm("mov.b64 {%0,%1},%2;" : "=f"(lo), "=f"(hi) : "l"(s))

// Interval endpoints from sign predicates + snapped distances (exact R10 math).
__device__ __forceinline__ void interval3(const float p[3], const float d[3],
                                          const bool pp[3], const bool nn[3],
                                          float& tmin, float& tmax) {
    tmin = INFINITY;
    tmax = -INFINITY;
#pragma unroll
    for (int k = 0; k < 3; k++) {
        const int kn = (k == 2) ? 0 : k + 1;
        bool valid = !((pp[k] & pp[kn]) | (nn[k] & nn[kn])) &
                     (pp[k] | nn[k] | pp[kn] | nn[kn]);
        float t = p[k] + (p[kn] - p[k]) * __fdividef(d[k], d[k] - d[kn]);
        if (valid) {
            tmin = fminf(tmin, t);
            tmax = fmaxf(tmax, t);
        }
    }
}

__device__ __forceinline__ float sel3(int ax, float x, float y, float z) {
    return (ax == 0) ? x : ((ax == 1) ? y : z);
}

// Scalar tail for one column-pair: snap, sign preds, argmax axis, selects,
// intervals, overlap. dvr/dur are the raw (unsnapped) distances.
__device__ __forceinline__ bool tail_test(const float dvr[3], const float dur[3],
                                          const float4 na, const float4 nb,
                                          const float2* __restrict__ aRow,
                                          const float Bh[9]) {
    float dv[3], du[3];
    bool pv_[3], nv_[3], pu_[3], nu_[3];
#pragma unroll
    for (int v = 0; v < 3; v++) {
        float dd = dvr[v];
        dd = (fabsf(dd) < EPS) ? 0.0f : dd;
        dv[v] = dd;
        pv_[v] = dd > 0.0f;
        nv_[v] = dd < 0.0f;
        float ee = dur[v];
        ee = (fabsf(ee) < EPS) ? 0.0f : ee;
        du[v] = ee;
        pu_[v] = ee > 0.0f;
        nu_[v] = ee < 0.0f;
    }

    bool ssv = (pv_[0] & pv_[1] & pv_[2]) | (nv_[0] & nv_[1] & nv_[2]);
    bool ssu = (pu_[0] & pu_[1] & pu_[2]) | (nu_[0] & nu_[1] & nu_[2]);

    // Dominant axis of na x nb (first-max argmax).
    float Dx = na.y * nb.z - na.z * nb.y;
    float Dy = na.z * nb.x - na.x * nb.z;
    float Dz = na.x * nb.y - na.y * nb.x;
    int ax = 0;
    float m = fabsf(Dx);
    if (fabsf(Dy) > m) { ax = 1; m = fabsf(Dy); }
    if (fabsf(Dz) > m) { ax = 2; }

    float pv[3], pu[3];
#pragma unroll
    for (int v = 0; v < 3; v++) {
        pv[v] = aRow[3 * v + ax].x;  // duplicated pair, lo lane
        pu[v] = sel3(ax, Bh[3 * v], Bh[3 * v + 1], Bh[3 * v + 2]);
    }

    float t0v, t1v, t0u, t1u;
    interval3(pv, dv, pv_, nv_, t0v, t1v);
    interval3(pu, du, pu_, nu_, t0u, t1u);
    return !ssv & !ssu & (fmaxf(t0v, t0u) <= fminf(t1v, t1u));
}

__device__ __forceinline__ int cum_rb(int p) { return RBPP * p * (p + 1) / 2; }

__global__ __launch_bounds__(HALFC, 8)
void pair_kernel(const float* __restrict__ T, float* __restrict__ out,
                 int N, int P) {
    // Linear tile id -> (panel p, row-block).
    const int k = blockIdx.x;
    int p = (int)((sqrtf(1.0f + (8.0f / RBPP) * (float)k) - 1.0f) * 0.5f);
    if (p > P - 1) p = P - 1;
    while (p + 1 <= P - 1 && cum_rb(p + 1) <= k) p++;
    while (p > 0 && cum_rb(p) > k) p--;
    const int c0 = p * COLSB;
    const int r0 = (k - cum_rb(p)) * ROWS;

    // Duplicated-lane shared: each entry packs {v, v} for free f32x2 operands.
    __shared__ ull sAd[ROWS][9];   // row triangle coords, duplicated
    __shared__ ull sPd[ROWS][4];   // row plane (n, d), duplicated

    const int tid = threadIdx.x;

    if (tid < ROWS * 9) {
        int r = tid / 9, c = tid % 9;
        int gi = r0 + r;
        float a = (gi < N) ? T[(size_t)gi * 9 + c] : 0.0f;
        ull pk;
        PACK2(pk, a, a);
        sAd[r][c] = pk;
    }
    __syncthreads();
    if (tid < ROWS) {
        float t[9];
#pragma unroll
        for (int c = 0; c < 9; c++) {
            float lo, hi;
            UNPACK2(lo, hi, sAd[tid][c]);
            t[c] = lo;
        }
        float e1x = t[3] - t[0], e1y = t[4] - t[1], e1z = t[5] - t[2];
        float e2x = t[6] - t[0], e2y = t[7] - t[1], e2z = t[8] - t[2];
        float nx = e1y * e2z - e1z * e2y;
        float ny = e1z * e2x - e1x * e2z;
        float nz = e1x * e2y - e1y * e2x;
        float nw = -(nx * t[0] + ny * t[1] + nz * t[2]);
        ull pk;
        PACK2(pk, nx, nx); sPd[tid][0] = pk;
        PACK2(pk, ny, ny); sPd[tid][1] = pk;
        PACK2(pk, nz, nz); sPd[tid][2] = pk;
        PACK2(pk, nw, nw); sPd[tid][3] = pk;
    }

    const int j1 = c0 + tid;
    const int j2 = c0 + HALFC + tid;
    const bool j1ok = j1 < N;
    const bool j2ok = j2 < N;
    const int j1c = j1ok ? j1 : (N - 1);
    const int j2c = j2ok ? j2 : (N - 1);

    // Two column triangles; keep scalar copies and packed {B1,B2} pairs.
    float B1[9], B2[9];
    const float* tb1 = T + (size_t)j1c * 9;
    const float* tb2 = T + (size_t)j2c * 9;
#pragma unroll
    for (int c = 0; c < 9; c++) {
        B1[c] = __ldg(tb1 + c);
        B2[c] = __ldg(tb2 + c);
    }
    ull Bp[9];
#pragma unroll
    for (int c = 0; c < 9; c++) PACK2(Bp[c], B1[c], B2[c]);

    float4 nb1, nb2;
    {
        float e1x = B1[3] - B1[0], e1y = B1[4] - B1[1], e1z = B1[5] - B1[2];
        float e2x = B1[6] - B1[0], e2y = B1[7] - B1[1], e2z = B1[8] - B1[2];
        nb1.x = e1y * e2z - e1z * e2y;
        nb1.y = e1z * e2x - e1x * e2z;
        nb1.z = e1x * e2y - e1y * e2x;
        nb1.w = -(nb1.x * B1[0] + nb1.y * B1[1] + nb1.z * B1[2]);
    }
    {
        float e1x = B2[3] - B2[0], e1y = B2[4] - B2[1], e1z = B2[5] - B2[2];
        float e2x = B2[6] - B2[0], e2y = B2[7] - B2[1], e2z = B2[8] - B2[2];
        nb2.x = e1y * e2z - e1z * e2y;
        nb2.y = e1z * e2x - e1x * e2z;
        nb2.z = e1x * e2y - e1y * e2x;
        nb2.w = -(nb2.x * B2[0] + nb2.y * B2[1] + nb2.z * B2[2]);
    }
    ull nbx, nby, nbz, nbw;
    PACK2(nbx, nb1.x, nb2.x);
    PACK2(nby, nb1.y, nb2.y);
    PACK2(nbz, nb1.z, nb2.z);
    PACK2(nbw, nb1.w, nb2.w);

    __syncthreads();

    const bool interior = (r0 + ROWS <= c0) && (c0 + COLSB <= N);

    unsigned hm1 = 0, hm2 = 0;

#pragma unroll
    for (int r = 0; r < ROWS; r++) {
        const int i = r0 + r;
        const ull* aR = sAd[r];
        const ull* nR = sPd[r];

        // Row plane scalars (lanes are duplicated; take lo).
        float4 na;
        {
            float lo, hi;
            UNPACK2(lo, hi, nR[0]); na.x = lo;
            UNPACK2(lo, hi, nR[1]); na.y = lo;
            UNPACK2(lo, hi, nR[2]); na.z = lo;
            UNPACK2(lo, hi, nR[3]); na.w = lo;
        }

        // Packed dots: lane0 = column j1, lane1 = column j2.
        float dv1[3], dv2[3], du1[3], du2[3];
#pragma unroll
        for (int v = 0; v < 3; v++) {
            // dd = fma(a0, nbx, fma(a1, nby, fma(a2, nbz, nbw)))
            ull acc = nbw;
            FMA2(acc, aR[3 * v + 2], nbz, acc);
            FMA2(acc, aR[3 * v + 1], nby, acc);
            FMA2(acc, aR[3 * v + 0], nbx, acc);
            UNPACK2(dv1[v], dv2[v], acc);
            // ee = fma(B0, nax, fma(B1, nay, fma(B2, naz, naw)))
            ull acc2 = nR[3];
            FMA2(acc2, Bp[3 * v + 2], nR[2], acc2);
            FMA2(acc2, Bp[3 * v + 1], nR[1], acc2);
            FMA2(acc2, Bp[3 * v + 0], nR[0], acc2);
            UNPACK2(du1[v], du2[v], acc2);
        }

        bool hit1 = tail_test(dv1, du1, na, nb1, (const float2*)aR, B1);
        bool hit2 = tail_test(dv2, du2, na, nb2, (const float2*)aR, B2);
        hm1 |= (hit1 ? 1u : 0u) << r;
        hm2 |= (hit2 ? 1u : 0u) << r;

        if (interior) {
            out[(size_t)i * N + j1] = hit1 ? 1.0f : 0.0f;  // coalesced
            out[(size_t)i * N + j2] = hit2 ? 1.0f : 0.0f;  // coalesced
        } else {
            if (i < N) {
                if (j1ok & (i <= j1)) {
                    out[(size_t)i * N + j1] =
                        (i == j1) ? 1.0f : (hit1 ? 1.0f : 0.0f);
                }
                if (j2ok & (i <= j2)) {
                    out[(size_t)i * N + j2] =
                        (i == j2) ? 1.0f : (hit2 ? 1.0f : 0.0f);
                }
            }
        }
    }

    // Mirror spans: cells (j, r0..r0+3).
    if (interior) {
        float4 v;
        v.x = (hm1 & 1u) ? 1.0f : 0.0f;
        v.y = (hm1 & 2u) ? 1.0f : 0.0f;
        v.z = (hm1 & 4u) ? 1.0f : 0.0f;
        v.w = (hm1 & 8u) ? 1.0f : 0.0f;
        *(float4*)(out + (size_t)j1 * N + r0) = v;
        v.x = (hm2 & 1u) ? 1.0f : 0.0f;
        v.y = (hm2 & 2u) ? 1.0f : 0.0f;
        v.z = (hm2 & 4u) ? 1.0f : 0.0f;
        v.w = (hm2 & 8u) ? 1.0f : 0.0f;
        *(float4*)(out + (size_t)j2 * N + r0) = v;
    } else {
        if (j1ok) {
            if (j1 >= r0 + ROWS && r0 + ROWS <= N) {
                float4 v;
                v.x = (hm1 & 1u) ? 1.0f : 0.0f;
                v.y = (hm1 & 2u) ? 1.0f : 0.0f;
                v.z = (hm1 & 4u) ? 1.0f : 0.0f;
                v.w = (hm1 & 8u) ? 1.0f : 0.0f;
                *(float4*)(out + (size_t)j1 * N + r0) = v;
            } else {
#pragma unroll
                for (int r = 0; r < ROWS; r++) {
                    int i = r0 + r;
                    if ((i < j1) & (i < N))
                        out[(size_t)j1 * N + i] = (hm1 >> r & 1u) ? 1.0f : 0.0f;
                }
            }
        }
        if (j2ok) {
            if (j2 >= r0 + ROWS && r0 + ROWS <= N) {
                float4 v;
                v.x = (hm2 & 1u) ? 1.0f : 0.0f;
                v.y = (hm2 & 2u) ? 1.0f : 0.0f;
                v.z = (hm2 & 4u) ? 1.0f : 0.0f;
                v.w = (hm2 & 8u) ? 1.0f : 0.0f;
                *(float4*)(out + (size_t)j2 * N + r0) = v;
            } else {
#pragma unroll
                for (int r = 0; r < ROWS; r++) {
                    int i = r0 + r;
                    if ((i < j2) & (i < N))
                        out[(size_t)j2 * N + i] = (hm2 >> r & 1u) ? 1.0f : 0.0f;
                }
            }
        }
    }
}

extern "C" void kernel_launch(void* const* d_in, const int* in_sizes, int n_in,
                              void* d_out, int out_size) {
    const float* T = (const float*)d_in[0];
    float* out = (float*)d_out;
    int N = in_sizes[0] / 9;

    int P = (N + COLSB - 1) / COLSB;
    int nblk = 0;
    for (int p = 0; p < P; p++) {
        int lim = (p + 1) * COLSB;
        if (lim > N) lim = N;
        nblk += (lim + ROWS - 1) / ROWS;
    }
    pair_kernel<<<nblk, HALFC>>>(T, out, N, P);
}

// round 13
// speedup vs baseline: 1.1631x; 1.1530x over previous
#include <cuda_runtime.h>
#include <math.h>

#define EPS 1e-6f
#define COLSB 128
#define ROWS 4
#define RBPP (COLSB / ROWS)  // row-blocks per full panel step

// Interval endpoints from sign predicates + snapped distances.
// valid_k == (di*dj<=0) & !(di==0 & dj==0) for snapped d (|d|>=EPS or 0).
// valid => di != dj, so the divide needs no guard.
__device__ __forceinline__ void interval3(const float p[3], const float d[3],
                                          const bool pp[3], const bool nn[3],
                                          float& tmin, float& tmax) {
    tmin = INFINITY;
    tmax = -INFINITY;
#pragma unroll
    for (int k = 0; k < 3; k++) {
        const int kn = (k == 2) ? 0 : k + 1;
        bool valid = !((pp[k] & pp[kn]) | (nn[k] & nn[kn])) &
                     (pp[k] | nn[k] | pp[kn] | nn[kn]);
        float t = p[k] + (p[kn] - p[k]) * __fdividef(d[k], d[k] - d[kn]);
        if (valid) {
            tmin = fminf(tmin, t);
            tmax = fmaxf(tmax, t);
        }
    }
}

__device__ __forceinline__ float sel3(int ax, float x, float y, float z) {
    return (ax == 0) ? x : ((ax == 1) ? y : z);
}

// Core pair test: triangle A (registers, loaded from shared broadcast) vs
// triangle B (registers). Snap via combined sign predicates:
//   pz = d>=EPS  <=> snapped>0 ;  nz = d<=-EPS <=> snapped<0 ;
//   snapped = (pz|nz) ? d : 0   (exactly the reference's snapped value).
__device__ __forceinline__ bool pair_test(const float* __restrict__ sa,
                                          const float4 na, const float* B,
                                          const float4 nb) {
    float A[9];
#pragma unroll
    for (int c = 0; c < 9; c++) A[c] = sa[c];

    float dv[3], du[3];
    bool pv_[3], nv_[3], pu_[3], nu_[3];
#pragma unroll
    for (int v = 0; v < 3; v++) {
        float dd = A[3 * v] * nb.x + A[3 * v + 1] * nb.y +
                   A[3 * v + 2] * nb.z + nb.w;
        bool pz = dd >= EPS;
        bool nz = dd <= -EPS;
        dv[v] = (pz | nz) ? dd : 0.0f;
        pv_[v] = pz;
        nv_[v] = nz;
        float ee = B[3 * v] * na.x + B[3 * v + 1] * na.y +
                   B[3 * v + 2] * na.z + na.w;
        bool pz2 = ee >= EPS;
        bool nz2 = ee <= -EPS;
        du[v] = (pz2 | nz2) ? ee : 0.0f;
        pu_[v] = pz2;
        nu_[v] = nz2;
    }

    bool ssv = (pv_[0] & pv_[1] & pv_[2]) | (nv_[0] & nv_[1] & nv_[2]);
    bool ssu = (pu_[0] & pu_[1] & pu_[2]) | (nu_[0] & nu_[1] & nu_[2]);

    // Dominant axis of na x nb (first-max argmax).
    float Dx = na.y * nb.z - na.z * nb.y;
    float Dy = na.z * nb.x - na.x * nb.z;
    float Dz = na.x * nb.y - na.y * nb.x;
    int ax = 0;
    float m = fabsf(Dx);
    if (fabsf(Dy) > m) { ax = 1; m = fabsf(Dy); }
    if (fabsf(Dz) > m) { ax = 2; }

    float pv[3], pu[3];
#pragma unroll
    for (int v = 0; v < 3; v++) {
        pv[v] = sel3(ax, A[3 * v], A[3 * v + 1], A[3 * v + 2]);
        pu[v] = sel3(ax, B[3 * v], B[3 * v + 1], B[3 * v + 2]);
    }

    float t0v, t1v, t0u, t1u;
    interval3(pv, dv, pv_, nv_, t0v, t1v);
    interval3(pu, du, pu_, nu_, t0u, t1u);
    return !ssv & !ssu & (fmaxf(t0v, t0u) <= fminf(t1v, t1u));
}

// Cumulative row-block count before panel p (valid for full panels).
__device__ __forceinline__ int cum_rb(int p) { return RBPP * p * (p + 1) / 2; }

__global__ __launch_bounds__(COLSB, 10)
void pair_kernel(const float* __restrict__ T, float* __restrict__ out,
                 int N, int P) {
    // O(1) decode: linear tile id -> (panel p, row-block).
    const int k = blockIdx.x;
    int p = (int)((sqrtf(1.0f + (8.0f / RBPP) * (float)k) - 1.0f) * 0.5f);
    if (p > P - 1) p = P - 1;
    while (p + 1 <= P - 1 && cum_rb(p + 1) <= k) p++;
    while (p > 0 && cum_rb(p) > k) p--;
    const int c0 = p * COLSB;
    const int r0 = (k - cum_rb(p)) * ROWS;

    __shared__ float sA[ROWS][9];
    __shared__ float4 sP[ROWS];

    const int tid = threadIdx.x;

    if (tid < ROWS * 9) {
        int r = tid / 9, c = tid % 9;
        int gi = r0 + r;
        sA[r][c] = (gi < N) ? T[(size_t)gi * 9 + c] : 0.0f;
    }
    __syncthreads();
    if (tid < ROWS) {
        const float* t = sA[tid];
        float e1x = t[3] - t[0], e1y = t[4] - t[1], e1z = t[5] - t[2];
        float e2x = t[6] - t[0], e2y = t[7] - t[1], e2z = t[8] - t[2];
        float nx = e1y * e2z - e1z * e2y;
        float ny = e1z * e2x - e1x * e2z;
        float nz = e1x * e2y - e1y * e2x;
        sP[tid] = make_float4(nx, ny, nz, -(nx * t[0] + ny * t[1] + nz * t[2]));
    }

    const int j = c0 + tid;
    const bool jok = j < N;
    const int jc = jok ? j : (N - 1);

    float B[9];
    const float* tb = T + (size_t)jc * 9;
#pragma unroll
    for (int c = 0; c < 9; c++) B[c] = __ldg(tb + c);
    float4 nb;
    {
        float e1x = B[3] - B[0], e1y = B[4] - B[1], e1z = B[5] - B[2];
        float e2x = B[6] - B[0], e2y = B[7] - B[1], e2z = B[8] - B[2];
        nb.x = e1y * e2z - e1z * e2y;
        nb.y = e1z * e2x - e1x * e2z;
        nb.z = e1x * e2y - e1y * e2x;
        nb.w = -(nb.x * B[0] + nb.y * B[1] + nb.z * B[2]);
    }
    __syncthreads();

    const bool interior = (r0 + ROWS <= c0) && (c0 + COLSB <= N);

    if (interior) {
        unsigned hitmask = 0;
#pragma unroll
        for (int r = 0; r < ROWS; r++) {
            bool hit = pair_test(sA[r], sP[r], B, nb);
            hitmask |= (hit ? 1u : 0u) << r;
            out[(size_t)(r0 + r) * N + j] = hit ? 1.0f : 0.0f;  // coalesced
        }
        float4 v0;
        v0.x = (hitmask & 1u) ? 1.0f : 0.0f;
        v0.y = (hitmask & 2u) ? 1.0f : 0.0f;
        v0.z = (hitmask & 4u) ? 1.0f : 0.0f;
        v0.w = (hitmask & 8u) ? 1.0f : 0.0f;
        *(float4*)(out + (size_t)j * N + r0) = v0;
    } else {
        unsigned hitmask = 0;
#pragma unroll
        for (int r = 0; r < ROWS; r++) {
            const int i = r0 + r;
            bool hit = pair_test(sA[r], sP[r], B, nb);
            hitmask |= (hit ? 1u : 0u) << r;
            float val = (i == j) ? 1.0f : (hit ? 1.0f : 0.0f);
            if (jok & (i <= j) & (i < N)) out[(size_t)i * N + j] = val;
        }
        if (jok) {
#pragma unroll
            for (int r = 0; r < ROWS; r++) {
                int i = r0 + r;
                if ((i < j) & (i < N))
                    out[(size_t)j * N + i] = (hitmask >> r & 1u) ? 1.0f : 0.0f;
            }
        }
    }
}

extern "C" void kernel_launch(void* const* d_in, const int* in_sizes, int n_in,
                              void* d_out, int out_size) {
    const float* T = (const float*)d_in[0];
    float* out = (float*)d_out;
    int N = in_sizes[0] / 9;

    int P = (N + COLSB - 1) / COLSB;
    int nblk = 0;
    for (int p = 0; p < P; p++) {
        int lim = (p + 1) * COLSB;
        if (lim > N) lim = N;
        nblk += (lim + ROWS - 1) / ROWS;
    }
    pair_kernel<<<nblk, COLSB>>>(T, out, N, P);
}

// round 14
// speedup vs baseline: 1.1750x; 1.0102x over previous
#include <cuda_runtime.h>
#include <math.h>

#define EPS 1e-6f
#define COLSB 128
#define ROWS 4
#define RBPP (COLSB / ROWS)  // row-blocks per full panel step

// Interval endpoints from sign predicates + snapped distances.
// valid_k == (di*dj<=0) & !(di==0 & dj==0) for snapped d (|d|>=EPS or 0).
// valid => di != dj, so the divide needs no guard.
__device__ __forceinline__ void interval3(const float p[3], const float d[3],
                                          const bool pp[3], const bool nn[3],
                                          float& tmin, float& tmax) {
    tmin = INFINITY;
    tmax = -INFINITY;
#pragma unroll
    for (int k = 0; k < 3; k++) {
        const int kn = (k == 2) ? 0 : k + 1;
        bool valid = !((pp[k] & pp[kn]) | (nn[k] & nn[kn])) &
                     (pp[k] | nn[k] | pp[kn] | nn[kn]);
        float t = p[k] + (p[kn] - p[k]) * __fdividef(d[k], d[k] - d[kn]);
        if (valid) {
            tmin = fminf(tmin, t);
            tmax = fmaxf(tmax, t);
        }
    }
}

__device__ __forceinline__ float sel3(int ax, float x, float y, float z) {
    return (ax == 0) ? x : ((ax == 1) ? y : z);
}

// Core pair test. Row triangle A arrives via 3x LDS.128 (padded 48B shared
// row, broadcast). Snap via combined sign predicates:
//   pz = d>=EPS <=> snapped>0 ; nz = d<=-EPS <=> snapped<0 ;
//   snapped = (pz|nz) ? d : 0  (exactly the reference's snapped value).
__device__ __forceinline__ bool pair_test(const float4* __restrict__ a4,
                                          const float4 na,
                                          const float* __restrict__ B,
                                          const float4 nb) {
    float4 A0 = a4[0], A1 = a4[1];
    float A8 = a4[2].x;
    float A[9] = {A0.x, A0.y, A0.z, A0.w, A1.x, A1.y, A1.z, A1.w, A8};

    float dv[3], du[3];
    bool pv_[3], nv_[3], pu_[3], nu_[3];
#pragma unroll
    for (int v = 0; v < 3; v++) {
        float dd = A[3 * v] * nb.x + A[3 * v + 1] * nb.y +
                   A[3 * v + 2] * nb.z + nb.w;
        bool pz = dd >= EPS;
        bool nz = dd <= -EPS;
        dv[v] = (pz | nz) ? dd : 0.0f;
        pv_[v] = pz;
        nv_[v] = nz;
        float ee = B[3 * v] * na.x + B[3 * v + 1] * na.y +
                   B[3 * v + 2] * na.z + na.w;
        bool pz2 = ee >= EPS;
        bool nz2 = ee <= -EPS;
        du[v] = (pz2 | nz2) ? ee : 0.0f;
        pu_[v] = pz2;
        nu_[v] = nz2;
    }

    bool ssv = (pv_[0] & pv_[1] & pv_[2]) | (nv_[0] & nv_[1] & nv_[2]);
    bool ssu = (pu_[0] & pu_[1] & pu_[2]) | (nu_[0] & nu_[1] & nu_[2]);

    // Dominant axis of na x nb (first-max argmax).
    float Dx = na.y * nb.z - na.z * nb.y;
    float Dy = na.z * nb.x - na.x * nb.z;
    float Dz = na.x * nb.y - na.y * nb.x;
    int ax = 0;
    float m = fabsf(Dx);
    if (fabsf(Dy) > m) { ax = 1; m = fabsf(Dy); }
    if (fabsf(Dz) > m) { ax = 2; }

    float pv[3], pu[3];
#pragma unroll
    for (int v = 0; v < 3; v++) {
        pv[v] = sel3(ax, A[3 * v], A[3 * v + 1], A[3 * v + 2]);
        pu[v] = sel3(ax, B[3 * v], B[3 * v + 1], B[3 * v + 2]);
    }

    float t0v, t1v, t0u, t1u;
    interval3(pv, dv, pv_, nv_, t0v, t1v);
    interval3(pu, du, pu_, nu_, t0u, t1u);
    return !ssv & !ssu & (fmaxf(t0v, t0u) <= fminf(t1v, t1u));
}

// Cumulative row-block count before panel p (valid for full panels).
__device__ __forceinline__ int cum_rb(int p) { return RBPP * p * (p + 1) / 2; }

__global__ __launch_bounds__(COLSB, 10)
void pair_kernel(const float* __restrict__ T, float* __restrict__ out,
                 int N, int P) {
    // O(1) decode: linear tile id -> (panel p, row-block).
    const int k = blockIdx.x;
    int p = (int)((sqrtf(1.0f + (8.0f / RBPP) * (float)k) - 1.0f) * 0.5f);
    if (p > P - 1) p = P - 1;
    while (p + 1 <= P - 1 && cum_rb(p + 1) <= k) p++;
    while (p > 0 && cum_rb(p) > k) p--;
    const int c0 = p * COLSB;
    const int r0 = (k - cum_rb(p)) * ROWS;

    __shared__ float sA[ROWS][12];  // 48B rows (16B-aligned) for LDS.128
    __shared__ float4 sP[ROWS];

    const int tid = threadIdx.x;

    if (tid < ROWS * 12) {
        int r = tid / 12, c = tid % 12;
        int gi = r0 + r;
        sA[r][c] = (c < 9 && gi < N) ? T[(size_t)gi * 9 + c] : 0.0f;
    }
    __syncthreads();
    if (tid < ROWS) {
        const float* t = sA[tid];
        float e1x = t[3] - t[0], e1y = t[4] - t[1], e1z = t[5] - t[2];
        float e2x = t[6] - t[0], e2y = t[7] - t[1], e2z = t[8] - t[2];
        float nx = e1y * e2z - e1z * e2y;
        float ny = e1z * e2x - e1x * e2z;
        float nz = e1x * e2y - e1y * e2x;
        sP[tid] = make_float4(nx, ny, nz, -(nx * t[0] + ny * t[1] + nz * t[2]));
    }

    const int j = c0 + tid;
    const bool jok = j < N;
    const int jc = jok ? j : (N - 1);

    float B[9];
    const float* tb = T + (size_t)jc * 9;
#pragma unroll
    for (int c = 0; c < 9; c++) B[c] = __ldg(tb + c);
    float4 nb;
    {
        float e1x = B[3] - B[0], e1y = B[4] - B[1], e1z = B[5] - B[2];
        float e2x = B[6] - B[0], e2y = B[7] - B[1], e2z = B[8] - B[2];
        nb.x = e1y * e2z - e1z * e2y;
        nb.y = e1z * e2x - e1x * e2z;
        nb.z = e1x * e2y - e1y * e2x;
        nb.w = -(nb.x * B[0] + nb.y * B[1] + nb.z * B[2]);
    }
    __syncthreads();

    const bool interior = (r0 + ROWS <= c0) && (c0 + COLSB <= N);

    if (interior) {
        unsigned hitmask = 0;
#pragma unroll
        for (int r = 0; r < ROWS; r++) {
            bool hit = pair_test((const float4*)sA[r], sP[r], B, nb);
            hitmask |= (hit ? 1u : 0u) << r;
            out[(size_t)(r0 + r) * N + j] = hit ? 1.0f : 0.0f;  // coalesced
        }
        float4 v0;
        v0.x = (hitmask & 1u) ? 1.0f : 0.0f;
        v0.y = (hitmask & 2u) ? 1.0f : 0.0f;
        v0.z = (hitmask & 4u) ? 1.0f : 0.0f;
        v0.w = (hitmask & 8u) ? 1.0f : 0.0f;
        *(float4*)(out + (size_t)j * N + r0) = v0;
    } else {
        unsigned hitmask = 0;
#pragma unroll
        for (int r = 0; r < ROWS; r++) {
            const int i = r0 + r;
            bool hit = pair_test((const float4*)sA[r], sP[r], B, nb);
            hitmask |= (hit ? 1u : 0u) << r;
            float val = (i == j) ? 1.0f : (hit ? 1.0f : 0.0f);
            if (jok & (i <= j) & (i < N)) out[(size_t)i * N + j] = val;
        }
        if (jok) {
#pragma unroll
            for (int r = 0; r < ROWS; r++) {
                int i = r0 + r;
                if ((i < j) & (i < N))
                    out[(size_t)j * N + i] = (hitmask >> r & 1u) ? 1.0f : 0.0f;
            }
        }
    }
}

extern "C" void kernel_launch(void* const* d_in, const int* in_sizes, int n_in,
                              void* d_out, int out_size) {
    const float* T = (const float*)d_in[0];
    float* out = (float*)d_out;
    int N = in_sizes[0] / 9;

    int P = (N + COLSB - 1) / COLSB;
    int nblk = 0;
    for (int p = 0; p < P; p++) {
        int lim = (p + 1) * COLSB;
        if (lim > N) lim = N;
        nblk += (lim + ROWS - 1) / ROWS;
    }
    pair_kernel<<<nblk, COLSB>>>(T, out, N, P);
}